// round 9
// baseline (speedup 1.0000x reference)
#include <cuda_runtime.h>
#include <cuda_bf16.h>
#include <cstdint>
#include <float.h>

#define W 128
#define BINS 50
#define NBOUND (BINS - 1)
#define MPAD 50
#define THREADS 256
#define NWARP (THREADS / 32)   // 8
#define GRID 384
#define G_SZ (BINS * W)        // floats per G buffer (6400)

// dynamic smem layout (floats): G[2][6400] | mtm[2500] | bins[128] | bnd[52] | smn[8] | smx[8] | mm[2]
#define SMEM_FLOATS (2 * G_SZ + BINS * MPAD + W + 52 + 8 + 8 + 2)
#define SMEM_BYTES  (SMEM_FLOATS * 4)

__global__ __launch_bounds__(THREADS)
void mtf_kernel(const float* __restrict__ X, float* __restrict__ out, int S) {
    extern __shared__ __align__(16) char smem_raw[];
    float* G    = reinterpret_cast<float*>(smem_raw);   // 2 buffers
    float* mtm  = G + 2 * G_SZ;
    int*   bins = reinterpret_cast<int*>(mtm + BINS * MPAD);
    float* bnd  = reinterpret_cast<float*>(bins + W);
    float* smn  = bnd + 52;
    float* smx  = smn + 8;
    float* mm   = smx + 8;    // [0]=min, [1]=max

    const int tid  = threadIdx.x;
    const int lane = tid & 31;
    const int wid  = tid >> 5;

    // Boundaries: linspace(-1, 1, 51)[1:-1]. (computed once)
    if (tid < NBOUND) {
        bnd[tid] = (float)(-1.0 + (2.0 * (double)(tid + 1)) / 50.0);
    }

    int ser = 0;
    for (int s = blockIdx.x; s < S; s += GRID, ser++) {
        float* Gb = G + (ser & 1) * G_SZ;

        // Before overwriting this buffer, ensure the bulk group that read it
        // (issued 2 series ago) has completed. Keep the most recent group in flight.
        if (ser >= 2 && tid < W) {
            asm volatile("cp.async.bulk.wait_group 1;" ::: "memory");
        }
        __syncthreads();

        // Clear transition counts.
        for (int i = tid; i < BINS * MPAD; i += THREADS) mtm[i] = 0.0f;

        // Load series values (threads 0..127) and block min/max.
        const float* x = X + (size_t)s * W;
        float v = 0.0f;
        if (tid < W) v = x[tid];
        float mn = (tid < W) ? v : FLT_MAX;
        float mx = (tid < W) ? v : -FLT_MAX;
        #pragma unroll
        for (int o = 16; o > 0; o >>= 1) {
            mn = fminf(mn, __shfl_xor_sync(0xFFFFFFFFu, mn, o));
            mx = fmaxf(mx, __shfl_xor_sync(0xFFFFFFFFu, mx, o));
        }
        if (lane == 0) { smn[wid] = mn; smx[wid] = mx; }
        __syncthreads();
        if (wid == 0) {
            float a = (lane < NWARP) ? smn[lane] : FLT_MAX;
            float b = (lane < NWARP) ? smx[lane] : -FLT_MAX;
            #pragma unroll
            for (int o = 4; o > 0; o >>= 1) {
                a = fminf(a, __shfl_xor_sync(0xFFFFFFFFu, a, o));
                b = fmaxf(b, __shfl_xor_sync(0xFFFFFFFFu, b, o));
            }
            if (lane == 0) { mm[0] = a; mm[1] = b; }
        }
        __syncthreads();

        // Scale into [-1,1] (same op order as reference) and bucketize.
        if (tid < W) {
            float denom = mm[1] - mm[0] + 1e-6f;
            float t = (v - mm[0]) / denom;
            float xsc = t * 2.0f + (-1.0f);
            int cnt = 0;
            #pragma unroll
            for (int k = 0; k < NBOUND; k++) cnt += (bnd[k] < xsc) ? 1 : 0;
            bins[tid] = cnt;
        }
        __syncthreads();

        // Transition histogram.
        if (tid < W - 1) {
            atomicAdd(&mtm[bins[tid] * MPAD + bins[tid + 1]], 1.0f);
        }
        // Each lane caches its 4 contiguous column bins (t2 = 4*lane..4*lane+3).
        const int4 c = reinterpret_cast<const int4*>(bins)[lane];
        __syncthreads();

        // Build the 50 distinct normalized rows into Gb.
        for (int b1 = wid; b1 < BINS; b1 += NWARP) {
            const float* row = &mtm[b1 * MPAD];
            float part = row[lane] + ((lane < BINS - 32) ? row[lane + 32] : 0.0f);
            #pragma unroll
            for (int off = 16; off > 0; off >>= 1)
                part += __shfl_xor_sync(0xFFFFFFFFu, part, off);
            float rinv = (part == 0.0f) ? 1.0f : (1.0f / part);

            float4 val;
            val.x = row[c.x] * rinv;
            val.y = row[c.y] * rinv;
            val.z = row[c.z] * rinv;
            val.w = row[c.w] * rinv;
            reinterpret_cast<float4*>(&Gb[b1 * W])[lane] = val;
        }
        __syncthreads();
        // Order generic-proxy STS writes of Gb before async-proxy reads.
        asm volatile("fence.proxy.async.shared::cta;" ::: "memory");

        // Each thread t1 issues one 512B bulk copy: Gb[bins[t1]] -> out row t1.
        if (tid < W) {
            uint32_t src;
            asm("{ .reg .u64 t; cvta.to.shared.u64 t, %1; cvt.u32.u64 %0, t; }"
                : "=r"(src) : "l"(&Gb[bins[tid] * W]));
            float* dst = out + (size_t)s * W * W + tid * W;
            asm volatile("cp.async.bulk.global.shared::cta.bulk_group [%0], [%1], %2;"
                         :: "l"(dst), "r"(src), "r"(W * 4) : "memory");
            asm volatile("cp.async.bulk.commit_group;" ::: "memory");
        }
        // No barrier here: next iteration's wait_group + syncthreads protects Gb.
    }

    // Drain everything before smem goes away.
    if (tid < W) {
        asm volatile("cp.async.bulk.wait_group 0;" ::: "memory");
    }
}

extern "C" void kernel_launch(void* const* d_in, const int* in_sizes, int n_in,
                              void* d_out, int out_size) {
    const float* X = (const float*)d_in[0];
    float* out = (float*)d_out;
    int S = in_sizes[0] / W;   // 1536 series
    cudaFuncSetAttribute(mtf_kernel, cudaFuncAttributeMaxDynamicSharedMemorySize, SMEM_BYTES);
    mtf_kernel<<<GRID, THREADS, SMEM_BYTES>>>(X, out, S);
}